// round 2
// baseline (speedup 1.0000x reference)
#include <cuda_runtime.h>
#include <math.h>

#define B_  4
#define C_  256
#define CQ_ 32
#define N_  4096
#define QT  64

// Scratch (allocation-free rule: __device__ globals)
__device__ float g_Q[(size_t)B_ * N_ * CQ_];
__device__ float g_K[(size_t)B_ * N_ * CQ_];
__device__ float g_V[(size_t)B_ * N_ * C_];

typedef unsigned long long u64;

__device__ __forceinline__ u64 pack2(float lo, float hi) {
    u64 r; asm("mov.b64 %0,{%1,%2};" : "=l"(r) : "f"(lo), "f"(hi)); return r;
}
__device__ __forceinline__ void unpack2(u64 v, float& lo, float& hi) {
    asm("mov.b64 {%0,%1},%2;" : "=f"(lo), "=f"(hi) : "l"(v));
}
__device__ __forceinline__ u64 fma2(u64 a, u64 b, u64 c) {
    u64 d; asm("fma.rn.f32x2 %0,%1,%2,%3;" : "=l"(d) : "l"(a), "l"(b), "l"(c)); return d;
}
__device__ __forceinline__ u64 mul2(u64 a, u64 b) {
    u64 d; asm("mul.rn.f32x2 %0,%1,%2;" : "=l"(d) : "l"(a), "l"(b)); return d;
}

// ---------------------------------------------------------------------------
// Kernel 1: QKV projection (1x1 conv). Grid: (N/64 pixel tiles, 5 out-groups, B)
// group 0 -> q(32)+k(32) (mask+bias applied), groups 1..4 -> v (64 ch each)
// ---------------------------------------------------------------------------
__global__ void __launch_bounds__(256) proj_kernel(
    const float* __restrict__ x, const float* __restrict__ mask,
    const float* __restrict__ Wq, const float* __restrict__ bq,
    const float* __restrict__ Wk, const float* __restrict__ bk,
    const float* __restrict__ Wv, const float* __restrict__ bv)
{
    __shared__ float xs[64 * 64];     // [cc][pixel]
    __shared__ float wsT[64 * 65];    // [cc][out], padded

    const int tid = threadIdx.x;
    const int tx = tid & 15, ty = tid >> 4;
    const int pix0 = blockIdx.x * 64;
    const int g = blockIdx.y;
    const int b = blockIdx.z;

    float acc[4][4];                  // [pp][rr]: pixel p=ty*4+pp, out o=tx+16*rr
#pragma unroll
    for (int i = 0; i < 4; i++)
#pragma unroll
        for (int j = 0; j < 4; j++) acc[i][j] = 0.f;

    for (int ch = 0; ch < 4; ch++) {
        const int c0 = ch * 64;
        __syncthreads();
        // load x chunk [64 ch x 64 pix]
        {
            const float4* X4 = (const float4*)x;
            float4* xs4 = (float4*)xs;
#pragma unroll
            for (int it = 0; it < 4; it++) {
                int e4 = tid + it * 256;
                int cc = e4 >> 4, p4 = e4 & 15;
                xs4[cc * 16 + p4] =
                    X4[(size_t)(b * C_ + c0 + cc) * (N_ / 4) + (pix0 >> 2) + p4];
            }
        }
        // load W chunk transposed [64 cc x 64 out]
        {
#pragma unroll
            for (int it = 0; it < 4; it++) {
                int e4 = tid + it * 256;
                int o = e4 >> 4, c4 = e4 & 15;
                const float* wrow;
                if (g == 0) wrow = (o < 32) ? (Wq + o * C_) : (Wk + (o - 32) * C_);
                else        wrow = Wv + ((g - 1) * 64 + o) * C_;
                float4 w4 = *(const float4*)(wrow + c0 + c4 * 4);
                wsT[(c4 * 4 + 0) * 65 + o] = w4.x;
                wsT[(c4 * 4 + 1) * 65 + o] = w4.y;
                wsT[(c4 * 4 + 2) * 65 + o] = w4.z;
                wsT[(c4 * 4 + 3) * 65 + o] = w4.w;
            }
        }
        __syncthreads();
#pragma unroll 8
        for (int cc = 0; cc < 64; cc++) {
            float xr[4], wr[4];
#pragma unroll
            for (int pp = 0; pp < 4; pp++) xr[pp] = xs[cc * 64 + ty * 4 + pp];
#pragma unroll
            for (int rr = 0; rr < 4; rr++) wr[rr] = wsT[cc * 65 + tx + 16 * rr];
#pragma unroll
            for (int pp = 0; pp < 4; pp++)
#pragma unroll
                for (int rr = 0; rr < 4; rr++)
                    acc[pp][rr] = fmaf(xr[pp], wr[rr], acc[pp][rr]);
        }
    }

    if (g == 0) {
#pragma unroll
        for (int pp = 0; pp < 4; pp++) {
            int p = ty * 4 + pp;
            float mv = mask[(b << 12) + pix0 + p];
#pragma unroll
            for (int rr = 0; rr < 4; rr++) {
                int o = tx + 16 * rr;
                if (o < 32) {
                    float v = (acc[pp][rr] + bq[o]) * mv;
                    g_Q[((size_t)(b << 12) + pix0 + p) * CQ_ + o] = v;
                } else {
                    float v = (acc[pp][rr] + bk[o - 32]) * mv;
                    g_K[((size_t)(b << 12) + pix0 + p) * CQ_ + (o - 32)] = v;
                }
            }
        }
    } else {
#pragma unroll
        for (int pp = 0; pp < 4; pp++) {
            int p = ty * 4 + pp;
#pragma unroll
            for (int rr = 0; rr < 4; rr++) {
                int vo = (g - 1) * 64 + tx + 16 * rr;
                g_V[((size_t)(b << 12) + pix0 + p) * C_ + vo] = acc[pp][rr] + bv[vo];
            }
        }
    }
}

// ---------------------------------------------------------------------------
// Kernel 2: fused flash attention + epilogue (gamma*out + x).
// Grid (N/64, B), 256 threads, online softmax, f32x2 packed FMA.
// Thread map: ty=tid/16, tx=tid%16; query rows i=ty*4+rr; S cols j=tx+16*cc;
// O channel pairs c2 = tx+16*k (channels 2*c2, 2*c2+1), k=0..7.
// ---------------------------------------------------------------------------
#define SM_QS 0                       // 64*32  = 2048 floats
#define SM_KS 2048                    // 64*34  = 2176 (pad: conflict-free f32x2)
#define SM_PS 4224                    // 64*65  = 4160
#define SM_VS 8384                    // max(64*256, 256*65) = 16640 (epilogue reuse)
#define SM_TOT 25024
#define SMEM_BYTES (SM_TOT * 4)

__global__ void __launch_bounds__(256, 2) attn_kernel(
    const float* __restrict__ x, const float* __restrict__ gamma,
    float* __restrict__ out)
{
    extern __shared__ float sm[];
    float* qs = sm + SM_QS;
    float* ks = sm + SM_KS;
    float* ps = sm + SM_PS;
    float* vs = sm + SM_VS;

    const int tid = threadIdx.x;
    const int tx = tid & 15, ty = tid >> 4;
    const int b = blockIdx.y;
    const int i0 = blockIdx.x * QT;

    // Q tile: contiguous copy (stride 32 floats = 16 f32x2 per row)
    {
        const float4* Q4 = (const float4*)(g_Q + ((size_t)(b << 12) + i0) * CQ_);
        float4* qs4 = (float4*)qs;
        qs4[tid] = Q4[tid];
        qs4[tid + 256] = Q4[tid + 256];
    }

    float m_[4], l_[4];
    u64 acc2[4][8];
#pragma unroll
    for (int rr = 0; rr < 4; rr++) {
        m_[rr] = -INFINITY; l_[rr] = 0.f;
#pragma unroll
        for (int k = 0; k < 8; k++) acc2[rr][k] = 0ULL;
    }

    const u64* qs2 = (const u64*)qs;
    const u64* ks2 = (const u64*)ks;
    const u64* vs2 = (const u64*)vs;

    for (int jt = 0; jt < 64; jt++) {
        const int j0 = jt * 64;
        __syncthreads();   // previous tile's ps/vs consumers done
        // K tile -> ks [col][kk], padded row stride 34 floats (17 f32x2)
        {
            const float2* K2 = (const float2*)(g_K + ((size_t)(b << 12) + j0) * CQ_);
            float2* ksw = (float2*)ks;
#pragma unroll
            for (int it = 0; it < 4; it++) {
                int e = tid + it * 256;
                int col = e >> 4, kp = e & 15;
                ksw[col * 17 + kp] = K2[col * 16 + kp];
            }
        }
        // V tile -> vs [j][c], 64x256 floats
        {
            const float4* V4 = (const float4*)(g_V + ((size_t)(b << 12) + j0) * C_);
            float4* vs4 = (float4*)vs;
#pragma unroll
            for (int it = 0; it < 16; it++) {
                int e = tid + it * 256;
                vs4[e] = V4[e];
            }
        }
        __syncthreads();

        // S tile (rows in two halves to bound register pressure) + online softmax
#pragma unroll
        for (int h = 0; h < 2; h++) {
            u64 sa[2][4];
#pragma unroll
            for (int r = 0; r < 2; r++)
#pragma unroll
                for (int cc = 0; cc < 4; cc++) sa[r][cc] = 0ULL;
#pragma unroll
            for (int kk = 0; kk < 16; kk++) {
                u64 q2[2], k2[4];
#pragma unroll
                for (int r = 0; r < 2; r++)
                    q2[r] = qs2[(ty * 4 + h * 2 + r) * 16 + kk];
#pragma unroll
                for (int cc = 0; cc < 4; cc++)
                    k2[cc] = ks2[(tx + 16 * cc) * 17 + kk];
#pragma unroll
                for (int r = 0; r < 2; r++)
#pragma unroll
                    for (int cc = 0; cc < 4; cc++)
                        sa[r][cc] = fma2(q2[r], k2[cc], sa[r][cc]);
            }
#pragma unroll
            for (int r = 0; r < 2; r++) {
                const int rr = h * 2 + r;
                float s[4];
#pragma unroll
                for (int cc = 0; cc < 4; cc++) {
                    float lo, hi; unpack2(sa[r][cc], lo, hi); s[cc] = lo + hi;
                }
                float tmax = fmaxf(fmaxf(s[0], s[1]), fmaxf(s[2], s[3]));
#pragma unroll
                for (int st = 1; st < 16; st <<= 1)
                    tmax = fmaxf(tmax, __shfl_xor_sync(0xffffffffu, tmax, st));
                float mnew = fmaxf(m_[rr], tmax);
                float alpha = __expf(m_[rr] - mnew);
                m_[rr] = mnew;
                float psum = 0.f;
#pragma unroll
                for (int cc = 0; cc < 4; cc++) { s[cc] = __expf(s[cc] - mnew); psum += s[cc]; }
#pragma unroll
                for (int st = 1; st < 16; st <<= 1)
                    psum += __shfl_xor_sync(0xffffffffu, psum, st);
                l_[rr] = l_[rr] * alpha + psum;
                u64 a2 = pack2(alpha, alpha);
#pragma unroll
                for (int k = 0; k < 8; k++) acc2[rr][k] = mul2(acc2[rr][k], a2);
#pragma unroll
                for (int cc = 0; cc < 4; cc++)
                    ps[(ty * 4 + rr) * 65 + tx + 16 * cc] = s[cc];
            }
        }
        __syncthreads();

        // O += P @ V  (f32x2 over channel pairs; conflict-free vs reads)
#pragma unroll 4
        for (int j = 0; j < 64; j++) {
            u64 p2[4];
#pragma unroll
            for (int rr = 0; rr < 4; rr++) {
                float pv = ps[(ty * 4 + rr) * 65 + j];
                p2[rr] = pack2(pv, pv);
            }
#pragma unroll
            for (int k = 0; k < 8; k++) {
                u64 v2 = vs2[j * 128 + tx + 16 * k];
#pragma unroll
                for (int rr = 0; rr < 4; rr++)
                    acc2[rr][k] = fma2(p2[rr], v2, acc2[rr][k]);
            }
        }
    }

    // Epilogue: normalize, stage transposed into smem (reuse vs as [c][i] stride 65),
    // then fully-coalesced out = gamma*O + x.
    __syncthreads();
    const float gm = gamma[0];
#pragma unroll
    for (int rr = 0; rr < 4; rr++) {
        float inv = 1.f / l_[rr];
        int i = ty * 4 + rr;
#pragma unroll
        for (int k = 0; k < 8; k++) {
            float lo, hi; unpack2(acc2[rr][k], lo, hi);
            int c = 2 * (tx + 16 * k);
            vs[c * 65 + i] = lo * inv;
            vs[(c + 1) * 65 + i] = hi * inv;
        }
    }
    __syncthreads();
    // FIX(R1): full 256ch x 64pix tile = 16384 elements (was 4096 -> 0.866 rel_err)
#pragma unroll
    for (int it = 0; it < 64; it++) {
        int e = tid + it * 256;
        int c = e >> 6, i = e & 63;
        size_t gidx = (((size_t)(b * C_ + c)) << 12) + i0 + i;
        out[gidx] = gm * vs[c * 65 + i] + x[gidx];
    }
}

// ---------------------------------------------------------------------------
extern "C" void kernel_launch(void* const* d_in, const int* in_sizes, int n_in,
                              void* d_out, int out_size)
{
    const float* x     = (const float*)d_in[0];
    const float* mask  = (const float*)d_in[1];
    const float* Wq    = (const float*)d_in[2];
    const float* bq    = (const float*)d_in[3];
    const float* Wk    = (const float*)d_in[4];
    const float* bk    = (const float*)d_in[5];
    const float* Wv    = (const float*)d_in[6];
    const float* bv    = (const float*)d_in[7];
    const float* gamma = (const float*)d_in[8];
    float* out = (float*)d_out;

    cudaFuncSetAttribute(attn_kernel,
                         cudaFuncAttributeMaxDynamicSharedMemorySize, SMEM_BYTES);

    dim3 pgrid(N_ / 64, 5, B_);
    proj_kernel<<<pgrid, 256>>>(x, mask, Wq, bq, Wk, bk, Wv, bv);

    dim3 agrid(N_ / QT, B_);
    attn_kernel<<<agrid, 256, SMEM_BYTES>>>(x, gamma, out);
}

// round 11
// speedup vs baseline: 3.0287x; 3.0287x over previous
#include <cuda_runtime.h>
#include <cuda_bf16.h>
#include <math.h>
#include <cstdint>

#define B_  4
#define C_  256
#define CQ_ 32
#define N_  4096

typedef unsigned int u32;
typedef unsigned long long u64;

// Scratch: Q/K plain f32 (exactly as proven R2); V bf16 channel-major [b][c][n]
__device__ float g_Q[(size_t)B_ * N_ * CQ_];
__device__ float g_K[(size_t)B_ * N_ * CQ_];
__device__ __align__(256) __nv_bfloat16 g_Vh[(size_t)B_ * C_ * N_];

__device__ __forceinline__ u32 smem_u32(const void* p) {
    u32 a; asm("{ .reg .u64 t; cvta.to.shared.u64 t, %1; cvt.u32.u64 %0, t; }"
               : "=r"(a) : "l"(p)); return a;
}
__device__ __forceinline__ u64 pack2(float lo, float hi) {
    u64 r; asm("mov.b64 %0,{%1,%2};" : "=l"(r) : "f"(lo), "f"(hi)); return r;
}
__device__ __forceinline__ void unpack2(u64 v, float& lo, float& hi) {
    asm("mov.b64 {%0,%1},%2;" : "=f"(lo), "=f"(hi) : "l"(v));
}
__device__ __forceinline__ u64 fma2(u64 a, u64 b, u64 c) {
    u64 d; asm("fma.rn.f32x2 %0,%1,%2,%3;" : "=l"(d) : "l"(a), "l"(b), "l"(c)); return d;
}
__device__ __forceinline__ void mma16(float* d, const u32* a, u32 b0, u32 b1) {
    asm volatile("mma.sync.aligned.m16n8k16.row.col.f32.bf16.bf16.f32 "
        "{%0,%1,%2,%3},{%4,%5,%6,%7},{%8,%9},{%0,%1,%2,%3};"
        : "+f"(d[0]), "+f"(d[1]), "+f"(d[2]), "+f"(d[3])
        : "r"(a[0]), "r"(a[1]), "r"(a[2]), "r"(a[3]), "r"(b0), "r"(b1));
}
__device__ __forceinline__ void ldsm4(u32& r0, u32& r1, u32& r2, u32& r3, u32 addr) {
    asm volatile("ldmatrix.sync.aligned.m8n8.x4.shared.b16 {%0,%1,%2,%3},[%4];"
                 : "=r"(r0), "=r"(r1), "=r"(r2), "=r"(r3) : "r"(addr));
}
#define CP16(dst, src) \
    asm volatile("cp.async.cg.shared.global [%0],[%1],16;" :: "r"(dst), "l"(src) : "memory")
#define CP_COMMIT() asm volatile("cp.async.commit_group;" ::: "memory")
#define CP_WAIT0()  asm volatile("cp.async.wait_group 0;" ::: "memory")

// ---------------------------------------------------------------------------
// Kernel 1: QKV projection — verbatim R2 (PASSED) except V goes to bf16
// channel-major scratch via one-line scalar stores.
// ---------------------------------------------------------------------------
__global__ void __launch_bounds__(256) proj_kernel(
    const float* __restrict__ x, const float* __restrict__ mask,
    const float* __restrict__ Wq, const float* __restrict__ bq,
    const float* __restrict__ Wk, const float* __restrict__ bk,
    const float* __restrict__ Wv, const float* __restrict__ bv)
{
    __shared__ float xs[64 * 64];
    __shared__ float wsT[64 * 65];

    const int tid = threadIdx.x;
    const int tx = tid & 15, ty = tid >> 4;
    const int pix0 = blockIdx.x * 64;
    const int g = blockIdx.y;
    const int b = blockIdx.z;

    float acc[4][4];
#pragma unroll
    for (int i = 0; i < 4; i++)
#pragma unroll
        for (int j = 0; j < 4; j++) acc[i][j] = 0.f;

    for (int ch = 0; ch < 4; ch++) {
        const int c0 = ch * 64;
        __syncthreads();
        {
            const float4* X4 = (const float4*)x;
            float4* xs4 = (float4*)xs;
#pragma unroll
            for (int it = 0; it < 4; it++) {
                int e4 = tid + it * 256;
                int cc = e4 >> 4, p4 = e4 & 15;
                xs4[cc * 16 + p4] =
                    X4[(size_t)(b * C_ + c0 + cc) * (N_ / 4) + (pix0 >> 2) + p4];
            }
        }
        {
#pragma unroll
            for (int it = 0; it < 4; it++) {
                int e4 = tid + it * 256;
                int o = e4 >> 4, c4 = e4 & 15;
                const float* wrow;
                if (g == 0) wrow = (o < 32) ? (Wq + o * C_) : (Wk + (o - 32) * C_);
                else        wrow = Wv + ((g - 1) * 64 + o) * C_;
                float4 w4 = *(const float4*)(wrow + c0 + c4 * 4);
                wsT[(c4 * 4 + 0) * 65 + o] = w4.x;
                wsT[(c4 * 4 + 1) * 65 + o] = w4.y;
                wsT[(c4 * 4 + 2) * 65 + o] = w4.z;
                wsT[(c4 * 4 + 3) * 65 + o] = w4.w;
            }
        }
        __syncthreads();
#pragma unroll 8
        for (int cc = 0; cc < 64; cc++) {
            float xr[4], wr[4];
#pragma unroll
            for (int pp = 0; pp < 4; pp++) xr[pp] = xs[cc * 64 + ty * 4 + pp];
#pragma unroll
            for (int rr = 0; rr < 4; rr++) wr[rr] = wsT[cc * 65 + tx + 16 * rr];
#pragma unroll
            for (int pp = 0; pp < 4; pp++)
#pragma unroll
                for (int rr = 0; rr < 4; rr++)
                    acc[pp][rr] = fmaf(xr[pp], wr[rr], acc[pp][rr]);
        }
    }

    if (g == 0) {
#pragma unroll
        for (int pp = 0; pp < 4; pp++) {
            int p = ty * 4 + pp;
            float mv = mask[(b << 12) + pix0 + p];
#pragma unroll
            for (int rr = 0; rr < 4; rr++) {
                int o = tx + 16 * rr;
                if (o < 32) {
                    g_Q[((size_t)(b << 12) + pix0 + p) * CQ_ + o] =
                        (acc[pp][rr] + bq[o]) * mv;
                } else {
                    g_K[((size_t)(b << 12) + pix0 + p) * CQ_ + (o - 32)] =
                        (acc[pp][rr] + bk[o - 32]) * mv;
                }
            }
        }
    } else {
#pragma unroll
        for (int pp = 0; pp < 4; pp++) {
            int p = ty * 4 + pp;
#pragma unroll
            for (int rr = 0; rr < 4; rr++) {
                int vo = (g - 1) * 64 + tx + 16 * rr;
                g_Vh[(((size_t)(b * C_ + vo)) << 12) + pix0 + p] =
                    __float2bfloat16_rn(acc[pp][rr] + bv[vo]);
            }
        }
    }
}

// ---------------------------------------------------------------------------
// Kernel 2: hybrid flash attention. Grid (64, B), 256 threads, 64 queries/CTA.
// S = QK^T + online softmax: VERBATIM R2 (proven). P@V: bf16 mma + ldmatrix.
// Interfaces between the two: plain arrays only (P[row][key], alpha[], linv[]).
// smem floats: qs[2048] ks[2176] alpha[64] linv[64] | P bf16 64x72 | V bf16 2x256x72
// ---------------------------------------------------------------------------
#define SM_QS    0
#define SM_KS    2048
#define SM_ALPHA 4224
#define SM_LINV  4288
#define P_OFF_B  17408                 // bytes (float idx 4352)
#define V0_OFF_B 26624
#define V1_OFF_B 63488
#define A_SMEM_BYTES 100352

__global__ void __launch_bounds__(256)
attn_kernel(const float* __restrict__ x, const float* __restrict__ gamma,
            float* __restrict__ out)
{
    extern __shared__ float sm[];
    const u32 sb = smem_u32(sm);
    float* qs = sm + SM_QS;
    float* ks = sm + SM_KS;
    float* alpha_s = sm + SM_ALPHA;
    float* linv = sm + SM_LINV;
    __nv_bfloat16* Pb = (__nv_bfloat16*)((char*)sm + P_OFF_B);

    const int tid = threadIdx.x;
    const int tx = tid & 15, ty = tid >> 4;       // S/softmax map (R2)
    const int w = tid >> 5, l = tid & 31;          // PV map
    const int rloc = l >> 2;
    const int wq = w & 3;                          // PV row group (16 rows)
    const int cb = (w >> 2) * 128;                 // PV chan base
    const int b = blockIdx.y;
    const int i0 = blockIdx.x * 64;

    // Q tile staging (R2 verbatim)
    {
        const float4* Q4 = (const float4*)(g_Q + ((size_t)(b << 12) + i0) * CQ_);
        float4* qs4 = (float4*)qs;
        qs4[tid] = Q4[tid];
        qs4[tid + 256] = Q4[tid + 256];
    }

    float m_[4], l_[4];
#pragma unroll
    for (int rr = 0; rr < 4; rr++) { m_[rr] = -INFINITY; l_[rr] = 0.f; }

    float oacc[16][4];
#pragma unroll
    for (int nt = 0; nt < 16; nt++)
#pragma unroll
        for (int i = 0; i < 4; i++) oacc[nt][i] = 0.f;

    const u64* qs2 = (const u64*)qs;
    const u64* ks2 = (const u64*)ks;
    const float* gKb = g_K + ((size_t)(b << 12)) * CQ_;
    const uint4* V4g = (const uint4*)g_Vh;

    // prologue: cp.async V tile 0
    {
#pragma unroll
        for (int it = 0; it < 8; it++) {
            int e = tid + it * 256;
            int chn = e >> 3, c = e & 7;
            CP16(sb + V0_OFF_B + chn * 144 + c * 16,
                 V4g + (((size_t)(b * C_ + chn)) << 9) + c);
        }
        CP_COMMIT();
    }

    for (int t = 0; t < 64; t++) {
        CP_WAIT0();
        __syncthreads();               // V[t] visible; prev PV done with P & V[t-1]

        if (t + 1 < 64) {
            const u32 vd = sb + (((t + 1) & 1) ? V1_OFF_B : V0_OFF_B);
#pragma unroll
            for (int it = 0; it < 8; it++) {
                int e = tid + it * 256;
                int chn = e >> 3, c = e & 7;
                CP16(vd + chn * 144 + c * 16,
                     V4g + (((size_t)(b * C_ + chn)) << 9) + (t + 1) * 8 + c);
            }
            CP_COMMIT();
        }

        // K tile staging (R2 verbatim): [key][chan] stride 34f, f32
        {
            const float2* K2 = (const float2*)(gKb + (size_t)t * 64 * CQ_);
            float2* ksw = (float2*)ks;
#pragma unroll
            for (int it = 0; it < 4; it++) {
                int e = tid + it * 256;
                int col = e >> 4, kp = e & 15;
                ksw[col * 17 + kp] = K2[col * 16 + kp];
            }
        }
        __syncthreads();

        // ---- S + online softmax: R2 VERBATIM, P->bf16 smem, alpha->smem ----
#pragma unroll
        for (int h = 0; h < 2; h++) {
            u64 sa[2][4];
#pragma unroll
            for (int r = 0; r < 2; r++)
#pragma unroll
                for (int cc = 0; cc < 4; cc++) sa[r][cc] = 0ULL;
#pragma unroll
            for (int kk = 0; kk < 16; kk++) {
                u64 q2[2], k2[4];
#pragma unroll
                for (int r = 0; r < 2; r++)
                    q2[r] = qs2[(ty * 4 + h * 2 + r) * 16 + kk];
#pragma unroll
                for (int cc = 0; cc < 4; cc++)
                    k2[cc] = ks2[(tx + 16 * cc) * 17 + kk];
#pragma unroll
                for (int r = 0; r < 2; r++)
#pragma unroll
                    for (int cc = 0; cc < 4; cc++)
                        sa[r][cc] = fma2(q2[r], k2[cc], sa[r][cc]);
            }
#pragma unroll
            for (int r = 0; r < 2; r++) {
                const int rr = h * 2 + r;
                float s[4];
#pragma unroll
                for (int cc = 0; cc < 4; cc++) {
                    float lo, hi; unpack2(sa[r][cc], lo, hi); s[cc] = lo + hi;
                }
                float tmax = fmaxf(fmaxf(s[0], s[1]), fmaxf(s[2], s[3]));
#pragma unroll
                for (int st = 1; st < 16; st <<= 1)
                    tmax = fmaxf(tmax, __shfl_xor_sync(0xffffffffu, tmax, st));
                float mnew = fmaxf(m_[rr], tmax);
                float alpha = __expf(m_[rr] - mnew);
                m_[rr] = mnew;
                float psum = 0.f;
#pragma unroll
                for (int cc = 0; cc < 4; cc++) { s[cc] = __expf(s[cc] - mnew); psum += s[cc]; }
#pragma unroll
                for (int st = 1; st < 16; st <<= 1)
                    psum += __shfl_xor_sync(0xffffffffu, psum, st);
                l_[rr] = l_[rr] * alpha + psum;
                if (tx == 0) alpha_s[ty * 4 + rr] = alpha;
#pragma unroll
                for (int cc = 0; cc < 4; cc++)
                    Pb[(ty * 4 + rr) * 72 + tx + 16 * cc] = __float2bfloat16_rn(s[cc]);
            }
        }
        __syncthreads();               // P + alpha visible to PV warps

        // ---- PV: bf16 mma. Warp wq rows [16wq,16wq+16), chans [cb,cb+128) ----
        {
            float a0 = alpha_s[16 * wq + rloc];
            float a1 = alpha_s[16 * wq + rloc + 8];
#pragma unroll
            for (int nt = 0; nt < 16; nt++) {
                oacc[nt][0] *= a0; oacc[nt][1] *= a0;
                oacc[nt][2] *= a1; oacc[nt][3] *= a1;
            }
            u32 pa[4][4];
#pragma unroll
            for (int kc = 0; kc < 4; kc++)
                ldsm4(pa[kc][0], pa[kc][1], pa[kc][2], pa[kc][3],
                      sb + P_OFF_B + ((16 * wq + (l & 15)) * 72 + kc * 16 + (l >> 4) * 8) * 2);
            const u32 vB = sb + ((t & 1) ? V1_OFF_B : V0_OFF_B);
#pragma unroll
            for (int kc = 0; kc < 4; kc++) {
#pragma unroll
                for (int np = 0; np < 8; np++) {
                    u32 v0, v1, v2, v3;
                    ldsm4(v0, v1, v2, v3,
                          vB + ((cb + 16 * np + (l & 7) + ((l >> 4) & 1) * 8) * 72
                                + kc * 16 + ((l >> 3) & 1) * 8) * 2);
                    mma16(oacc[2 * np],     pa[kc], v0, v1);
                    mma16(oacc[2 * np + 1], pa[kc], v2, v3);
                }
            }
        }
    }

    // ---- finalize: linv[row] = gamma / l (plain array) ----
    const float gm = gamma[0];
    if (tx == 0) {
#pragma unroll
        for (int rr = 0; rr < 4; rr++) linv[ty * 4 + rr] = gm / l_[rr];
    }
    __syncthreads();

    // ---- epilogue: two 128-chan phases via smem transpose ts[cl][row] s68 ----
    float g0 = linv[16 * wq + rloc];
    float g1 = linv[16 * wq + rloc + 8];
    float* ts = sm;
    const int kq = l & 3;
#pragma unroll 1
    for (int ph = 0; ph < 2; ph++) {
        __syncthreads();
        if ((w >> 2) == ph) {
            int row0 = 16 * wq + rloc, row1 = row0 + 8;
#pragma unroll
            for (int np = 0; np < 8; np++) {
                int cl0 = 16 * np + 2 * kq;
                int cl1 = 16 * np + 8 + 2 * kq;
                ts[cl0 * 68 + row0]       = oacc[2 * np][0] * g0;
                ts[(cl0 + 1) * 68 + row0] = oacc[2 * np][1] * g0;
                ts[cl0 * 68 + row1]       = oacc[2 * np][2] * g1;
                ts[(cl0 + 1) * 68 + row1] = oacc[2 * np][3] * g1;
                ts[cl1 * 68 + row0]       = oacc[2 * np + 1][0] * g0;
                ts[(cl1 + 1) * 68 + row0] = oacc[2 * np + 1][1] * g0;
                ts[cl1 * 68 + row1]       = oacc[2 * np + 1][2] * g1;
                ts[(cl1 + 1) * 68 + row1] = oacc[2 * np + 1][3] * g1;
            }
        }
        __syncthreads();
#pragma unroll
        for (int it = 0; it < 8; it++) {
            int e = tid + it * 256;
            int c = e >> 4, r4 = e & 15;
            float4 o4 = *(const float4*)(ts + c * 68 + r4 * 4);
            size_t g4 = (size_t)(b * C_ + ph * 128 + c) * 1024 + (i0 >> 2) + r4;
            float4 x4 = ((const float4*)x)[g4];
            o4.x += x4.x; o4.y += x4.y; o4.z += x4.z; o4.w += x4.w;
            ((float4*)out)[g4] = o4;
        }
    }
}

// ---------------------------------------------------------------------------
extern "C" void kernel_launch(void* const* d_in, const int* in_sizes, int n_in,
                              void* d_out, int out_size)
{
    const float* x     = (const float*)d_in[0];
    const float* mask  = (const float*)d_in[1];
    const float* Wq    = (const float*)d_in[2];
    const float* bq    = (const float*)d_in[3];
    const float* Wk    = (const float*)d_in[4];
    const float* bk    = (const float*)d_in[5];
    const float* Wv    = (const float*)d_in[6];
    const float* bv    = (const float*)d_in[7];
    const float* gamma = (const float*)d_in[8];
    float* out = (float*)d_out;

    cudaFuncSetAttribute(attn_kernel,
                         cudaFuncAttributeMaxDynamicSharedMemorySize, A_SMEM_BYTES);

    dim3 pgrid(N_ / 64, 5, B_);
    proj_kernel<<<pgrid, 256>>>(x, mask, Wq, bq, Wk, bk, Wv, bv);

    dim3 agrid(N_ / 64, B_);
    attn_kernel<<<agrid, 256, A_SMEM_BYTES>>>(x, gamma, out);
}

// round 12
// speedup vs baseline: 5.0202x; 1.6575x over previous
#include <cuda_runtime.h>
#include <cuda_bf16.h>
#include <math.h>
#include <cstdint>

#define B_  4
#define C_  256
#define CQ_ 32
#define N_  4096

typedef unsigned int u32;
typedef unsigned long long u64;

// bf16 scratch: Q/K [b][n][32]; V channel-major [b][c][n]
__device__ __align__(256) __nv_bfloat16 g_Qh[(size_t)B_ * N_ * CQ_];
__device__ __align__(256) __nv_bfloat16 g_Kh[(size_t)B_ * N_ * CQ_];
__device__ __align__(256) __nv_bfloat16 g_Vh[(size_t)B_ * C_ * N_];

__device__ __forceinline__ u32 smem_u32(const void* p) {
    u32 a; asm("{ .reg .u64 t; cvta.to.shared.u64 t, %1; cvt.u32.u64 %0, t; }"
               : "=r"(a) : "l"(p)); return a;
}
__device__ __forceinline__ u32 bf2pack(float lo, float hi) {
    u32 r;
    asm("{ .reg .b16 a,b; cvt.rn.bf16.f32 a,%1; cvt.rn.bf16.f32 b,%2; mov.b32 %0,{a,b}; }"
        : "=r"(r) : "f"(lo), "f"(hi));
    return r;
}
__device__ __forceinline__ void mma16(float* d, const u32* a, u32 b0, u32 b1) {
    asm volatile("mma.sync.aligned.m16n8k16.row.col.f32.bf16.bf16.f32 "
        "{%0,%1,%2,%3},{%4,%5,%6,%7},{%8,%9},{%0,%1,%2,%3};"
        : "+f"(d[0]), "+f"(d[1]), "+f"(d[2]), "+f"(d[3])
        : "r"(a[0]), "r"(a[1]), "r"(a[2]), "r"(a[3]), "r"(b0), "r"(b1));
}
__device__ __forceinline__ void ldsm4(u32& r0, u32& r1, u32& r2, u32& r3, u32 addr) {
    asm volatile("ldmatrix.sync.aligned.m8n8.x4.shared.b16 {%0,%1,%2,%3},[%4];"
                 : "=r"(r0), "=r"(r1), "=r"(r2), "=r"(r3) : "r"(addr));
}
#define CP16(dst, src) \
    asm volatile("cp.async.cg.shared.global [%0],[%1],16;" :: "r"(dst), "l"(src) : "memory")
#define CP_COMMIT() asm volatile("cp.async.commit_group;" ::: "memory")
#define CP_WAIT0()  asm volatile("cp.async.wait_group 0;" ::: "memory")

// ---------------------------------------------------------------------------
// Kernel 1: QKV projection — R2-proven GEMM core; bf16 scalar stores (the
// exact store style proven by R11's V path) for Q, K, and channel-major V.
// ---------------------------------------------------------------------------
__global__ void __launch_bounds__(256) proj_kernel(
    const float* __restrict__ x, const float* __restrict__ mask,
    const float* __restrict__ Wq, const float* __restrict__ bq,
    const float* __restrict__ Wk, const float* __restrict__ bk,
    const float* __restrict__ Wv, const float* __restrict__ bv)
{
    __shared__ float xs[64 * 64];
    __shared__ float wsT[64 * 65];

    const int tid = threadIdx.x;
    const int tx = tid & 15, ty = tid >> 4;
    const int pix0 = blockIdx.x * 64;
    const int g = blockIdx.y;
    const int b = blockIdx.z;

    float acc[4][4];
#pragma unroll
    for (int i = 0; i < 4; i++)
#pragma unroll
        for (int j = 0; j < 4; j++) acc[i][j] = 0.f;

    for (int ch = 0; ch < 4; ch++) {
        const int c0 = ch * 64;
        __syncthreads();
        {
            const float4* X4 = (const float4*)x;
            float4* xs4 = (float4*)xs;
#pragma unroll
            for (int it = 0; it < 4; it++) {
                int e4 = tid + it * 256;
                int cc = e4 >> 4, p4 = e4 & 15;
                xs4[cc * 16 + p4] =
                    X4[(size_t)(b * C_ + c0 + cc) * (N_ / 4) + (pix0 >> 2) + p4];
            }
        }
        {
#pragma unroll
            for (int it = 0; it < 4; it++) {
                int e4 = tid + it * 256;
                int o = e4 >> 4, c4 = e4 & 15;
                const float* wrow;
                if (g == 0) wrow = (o < 32) ? (Wq + o * C_) : (Wk + (o - 32) * C_);
                else        wrow = Wv + ((g - 1) * 64 + o) * C_;
                float4 w4 = *(const float4*)(wrow + c0 + c4 * 4);
                wsT[(c4 * 4 + 0) * 65 + o] = w4.x;
                wsT[(c4 * 4 + 1) * 65 + o] = w4.y;
                wsT[(c4 * 4 + 2) * 65 + o] = w4.z;
                wsT[(c4 * 4 + 3) * 65 + o] = w4.w;
            }
        }
        __syncthreads();
#pragma unroll 8
        for (int cc = 0; cc < 64; cc++) {
            float xr[4], wr[4];
#pragma unroll
            for (int pp = 0; pp < 4; pp++) xr[pp] = xs[cc * 64 + ty * 4 + pp];
#pragma unroll
            for (int rr = 0; rr < 4; rr++) wr[rr] = wsT[cc * 65 + tx + 16 * rr];
#pragma unroll
            for (int pp = 0; pp < 4; pp++)
#pragma unroll
                for (int rr = 0; rr < 4; rr++)
                    acc[pp][rr] = fmaf(xr[pp], wr[rr], acc[pp][rr]);
        }
    }

    if (g == 0) {
#pragma unroll
        for (int pp = 0; pp < 4; pp++) {
            int p = ty * 4 + pp;
            float mv = mask[(b << 12) + pix0 + p];
#pragma unroll
            for (int rr = 0; rr < 4; rr++) {
                int o = tx + 16 * rr;
                if (o < 32) {
                    g_Qh[((size_t)(b << 12) + pix0 + p) * CQ_ + o] =
                        __float2bfloat16_rn((acc[pp][rr] + bq[o]) * mv);
                } else {
                    g_Kh[((size_t)(b << 12) + pix0 + p) * CQ_ + (o - 32)] =
                        __float2bfloat16_rn((acc[pp][rr] + bk[o - 32]) * mv);
                }
            }
        }
    } else {
#pragma unroll
        for (int pp = 0; pp < 4; pp++) {
            int p = ty * 4 + pp;
#pragma unroll
            for (int rr = 0; rr < 4; rr++) {
                int vo = (g - 1) * 64 + tx + 16 * rr;
                g_Vh[(((size_t)(b * C_ + vo)) << 12) + pix0 + p] =
                    __float2bfloat16_rn(acc[pp][rr] + bv[vo]);
            }
        }
    }
}

// ---------------------------------------------------------------------------
// Kernel 2: full-tensor flash attention. Grid (64, B), 256 thr, 64 q/CTA.
// QK mma = structural clone of R11's proven PV block (Q<-P, K<-V patterns).
// Warps 0-3: S + softmax (rows 16w..16w+16). All warps: PV (R11 verbatim).
// smem bytes: Q[64x80] | K0,K1[64x80] | V0,V1[256x144] | P[64x144] | alpha | linv
// ---------------------------------------------------------------------------
#define QOFF_B  0
#define K0_B    5120
#define K1_B    10240
#define V0_B    15360
#define V1_B    52224
#define P_B     89088
#define ALPHA_F 24576            /* float index (byte 98304) */
#define LINV_F  24640
#define A_SMEM_BYTES 98816

__global__ void __launch_bounds__(256)
attn_kernel(const float* __restrict__ x, const float* __restrict__ gamma,
            float* __restrict__ out)
{
    extern __shared__ float sm[];
    char* smem8 = (char*)sm;
    const u32 sb = smem_u32(sm);
    float* alpha_s = sm + ALPHA_F;
    float* linv = sm + LINV_F;

    const int tid = threadIdx.x;
    const int w = tid >> 5, l = tid & 31;
    const int kq = l & 3, rloc = l >> 2;
    const int wq = w & 3;                       // row group (16 rows)
    const int cb = (w >> 2) * 128;              // PV channel base
    const int b = blockIdx.y;
    const int i0 = blockIdx.x * 64;

    const uint4* Q4g = (const uint4*)g_Qh;
    const uint4* K4g = (const uint4*)g_Kh;
    const uint4* V4g = (const uint4*)g_Vh;

    // ---- prologue: stage Q (plain stores); cp.async K0 + V0 ----
    {
        int row = tid >> 2, c = tid & 3;
        *(uint4*)(smem8 + QOFF_B + row * 80 + c * 16) =
            Q4g[((size_t)((b << 12) + i0 + row)) * 4 + c];
        CP16(sb + K0_B + row * 80 + c * 16,
             K4g + ((size_t)(b << 12) + row) * 4 + c);
#pragma unroll
        for (int it = 0; it < 8; it++) {
            int e = tid + it * 256;
            int chn = e >> 3, cc = e & 7;
            CP16(sb + V0_B + chn * 144 + cc * 16,
                 V4g + (((size_t)(b * C_ + chn)) << 9) + cc);
        }
        CP_COMMIT();
    }
    __syncthreads();

    // Q A-frags (clone of R11 pa pattern; stride 40 halves, kc 0..1)
    u32 qa[2][4];
#pragma unroll
    for (int kc = 0; kc < 2; kc++)
        ldsm4(qa[kc][0], qa[kc][1], qa[kc][2], qa[kc][3],
              sb + QOFF_B + ((16 * wq + (l & 15)) * 40 + kc * 16 + (l >> 4) * 8) * 2);

    float oacc[16][4];
#pragma unroll
    for (int nt = 0; nt < 16; nt++)
#pragma unroll
        for (int i = 0; i < 4; i++) oacc[nt][i] = 0.f;
    float m0 = -INFINITY, m1 = -INFINITY, l0s = 0.f, l1s = 0.f;

    for (int t = 0; t < 64; t++) {
        CP_WAIT0();
        __syncthreads();            // K[t],V[t] ready; prev readers of bufs done

        if (t + 1 < 64) {
            const u32 kd = sb + (((t + 1) & 1) ? K1_B : K0_B);
            const u32 vd = sb + (((t + 1) & 1) ? V1_B : V0_B);
            int row = tid >> 2, c = tid & 3;
            CP16(kd + row * 80 + c * 16,
                 K4g + ((size_t)((b << 12) + (t + 1) * 64 + row)) * 4 + c);
#pragma unroll
            for (int it = 0; it < 8; it++) {
                int e = tid + it * 256;
                int chn = e >> 3, cc = e & 7;
                CP16(vd + chn * 144 + cc * 16,
                     V4g + (((size_t)(b * C_ + chn)) << 9) + (t + 1) * 8 + cc);
            }
            CP_COMMIT();
        }

        // ---- S = Q K^T + softmax: warps 0-3 only ----
        if (w < 4) {
            const u32 kB = sb + ((t & 1) ? K1_B : K0_B);
            float s[8][4];
#pragma unroll
            for (int nt = 0; nt < 8; nt++)
#pragma unroll
                for (int i = 0; i < 4; i++) s[nt][i] = 0.f;
            // clone of R11 V-ldsm loop: keys<-chans, stride 40, kc 0..1
#pragma unroll
            for (int kc = 0; kc < 2; kc++) {
#pragma unroll
                for (int np = 0; np < 4; np++) {
                    u32 k0, k1, k2, k3;
                    ldsm4(k0, k1, k2, k3,
                          kB + ((16 * np + (l & 7) + ((l >> 4) & 1) * 8) * 40
                                + kc * 16 + ((l >> 3) & 1) * 8) * 2);
                    mma16(s[2 * np],     qa[kc], k0, k1);
                    mma16(s[2 * np + 1], qa[kc], k2, k3);
                }
            }
            // softmax on D layout: rows 16w+rloc, +8
            float rm0 = -INFINITY, rm1 = -INFINITY;
#pragma unroll
            for (int nt = 0; nt < 8; nt++) {
                rm0 = fmaxf(rm0, fmaxf(s[nt][0], s[nt][1]));
                rm1 = fmaxf(rm1, fmaxf(s[nt][2], s[nt][3]));
            }
            rm0 = fmaxf(rm0, __shfl_xor_sync(0xffffffffu, rm0, 1));
            rm0 = fmaxf(rm0, __shfl_xor_sync(0xffffffffu, rm0, 2));
            rm1 = fmaxf(rm1, __shfl_xor_sync(0xffffffffu, rm1, 1));
            rm1 = fmaxf(rm1, __shfl_xor_sync(0xffffffffu, rm1, 2));
            float mn0 = fmaxf(m0, rm0), mn1 = fmaxf(m1, rm1);
            float al0 = __expf(m0 - mn0), al1 = __expf(m1 - mn1);
            m0 = mn0; m1 = mn1;
            float ps0 = 0.f, ps1 = 0.f;
#pragma unroll
            for (int nt = 0; nt < 8; nt++) {
                s[nt][0] = __expf(s[nt][0] - mn0);
                s[nt][1] = __expf(s[nt][1] - mn0);
                s[nt][2] = __expf(s[nt][2] - mn1);
                s[nt][3] = __expf(s[nt][3] - mn1);
                ps0 += s[nt][0] + s[nt][1];
                ps1 += s[nt][2] + s[nt][3];
            }
            ps0 += __shfl_xor_sync(0xffffffffu, ps0, 1);
            ps0 += __shfl_xor_sync(0xffffffffu, ps0, 2);
            ps1 += __shfl_xor_sync(0xffffffffu, ps1, 1);
            ps1 += __shfl_xor_sync(0xffffffffu, ps1, 2);
            l0s = l0s * al0 + ps0;
            l1s = l1s * al1 + ps1;
            if (kq == 0) {
                alpha_s[16 * w + rloc] = al0;
                alpha_s[16 * w + rloc + 8] = al1;
            }
            // P store via D-layout addressing (proven by R11 epilogue)
#pragma unroll
            for (int nt = 0; nt < 8; nt++) {
                *(u32*)(smem8 + P_B + ((16 * w + rloc) * 72 + 8 * nt + 2 * kq) * 2) =
                    bf2pack(s[nt][0], s[nt][1]);
                *(u32*)(smem8 + P_B + ((16 * w + rloc + 8) * 72 + 8 * nt + 2 * kq) * 2) =
                    bf2pack(s[nt][2], s[nt][3]);
            }
        }
        __syncthreads();            // P + alpha visible

        // ---- PV: R11 verbatim ----
        {
            float a0 = alpha_s[16 * wq + rloc];
            float a1 = alpha_s[16 * wq + rloc + 8];
            if (!__all_sync(0xffffffffu, (a0 == 1.f) && (a1 == 1.f))) {
#pragma unroll
                for (int nt = 0; nt < 16; nt++) {
                    oacc[nt][0] *= a0; oacc[nt][1] *= a0;
                    oacc[nt][2] *= a1; oacc[nt][3] *= a1;
                }
            }
            u32 pa[4][4];
#pragma unroll
            for (int kc = 0; kc < 4; kc++)
                ldsm4(pa[kc][0], pa[kc][1], pa[kc][2], pa[kc][3],
                      sb + P_B + ((16 * wq + (l & 15)) * 72 + kc * 16 + (l >> 4) * 8) * 2);
            const u32 vB = sb + ((t & 1) ? V1_B : V0_B);
#pragma unroll
            for (int kc = 0; kc < 4; kc++) {
#pragma unroll
                for (int np = 0; np < 8; np++) {
                    u32 v0, v1, v2, v3;
                    ldsm4(v0, v1, v2, v3,
                          vB + ((cb + 16 * np + (l & 7) + ((l >> 4) & 1) * 8) * 72
                                + kc * 16 + ((l >> 3) & 1) * 8) * 2);
                    mma16(oacc[2 * np],     pa[kc], v0, v1);
                    mma16(oacc[2 * np + 1], pa[kc], v2, v3);
                }
            }
        }
    }

    // ---- finalize ----
    const float gm = gamma[0];
    if (w < 4 && kq == 0) {
        linv[16 * w + rloc] = gm / l0s;
        linv[16 * w + rloc + 8] = gm / l1s;
    }
    __syncthreads();

    // ---- epilogue: R11 verbatim ----
    float g0 = linv[16 * wq + rloc];
    float g1 = linv[16 * wq + rloc + 8];
    float* ts = sm;
#pragma unroll 1
    for (int ph = 0; ph < 2; ph++) {
        __syncthreads();
        if ((w >> 2) == ph) {
            int row0 = 16 * wq + rloc, row1 = row0 + 8;
#pragma unroll
            for (int np = 0; np < 8; np++) {
                int cl0 = 16 * np + 2 * kq;
                int cl1 = 16 * np + 8 + 2 * kq;
                ts[cl0 * 68 + row0]       = oacc[2 * np][0] * g0;
                ts[(cl0 + 1) * 68 + row0] = oacc[2 * np][1] * g0;
                ts[cl0 * 68 + row1]       = oacc[2 * np][2] * g1;
                ts[(cl0 + 1) * 68 + row1] = oacc[2 * np][3] * g1;
                ts[cl1 * 68 + row0]       = oacc[2 * np + 1][0] * g0;
                ts[(cl1 + 1) * 68 + row0] = oacc[2 * np + 1][1] * g0;
                ts[cl1 * 68 + row1]       = oacc[2 * np + 1][2] * g1;
                ts[(cl1 + 1) * 68 + row1] = oacc[2 * np + 1][3] * g1;
            }
        }
        __syncthreads();
#pragma unroll
        for (int it = 0; it < 8; it++) {
            int e = tid + it * 256;
            int c = e >> 4, r4 = e & 15;
            float4 o4 = *(const float4*)(ts + c * 68 + r4 * 4);
            size_t g4 = (size_t)(b * C_ + ph * 128 + c) * 1024 + (i0 >> 2) + r4;
            float4 x4 = ((const float4*)x)[g4];
            o4.x += x4.x; o4.y += x4.y; o4.z += x4.z; o4.w += x4.w;
            ((float4*)out)[g4] = o4;
        }
    }
}

// ---------------------------------------------------------------------------
extern "C" void kernel_launch(void* const* d_in, const int* in_sizes, int n_in,
                              void* d_out, int out_size)
{
    const float* x     = (const float*)d_in[0];
    const float* mask  = (const float*)d_in[1];
    const float* Wq    = (const float*)d_in[2];
    const float* bq    = (const float*)d_in[3];
    const float* Wk    = (const float*)d_in[4];
    const float* bk    = (const float*)d_in[5];
    const float* Wv    = (const float*)d_in[6];
    const float* bv    = (const float*)d_in[7];
    const float* gamma = (const float*)d_in[8];
    float* out = (float*)d_out;

    cudaFuncSetAttribute(attn_kernel,
                         cudaFuncAttributeMaxDynamicSharedMemorySize, A_SMEM_BYTES);

    dim3 pgrid(N_ / 64, 5, B_);
    proj_kernel<<<pgrid, 256>>>(x, mask, Wq, bq, Wk, bk, Wv, bv);

    dim3 agrid(N_ / 64, B_);
    attn_kernel<<<agrid, 256, A_SMEM_BYTES>>>(x, gamma, out);
}